// round 2
// baseline (speedup 1.0000x reference)
#include <cuda_runtime.h>
#include <cooperative_groups.h>
#include <cstdint>
#include <math.h>

namespace cg = cooperative_groups;

#define BLOCK 512
#define CLUSTER 4
#define CAP 32

// shared-memory layout (in floats)
#define OFF_X0    0        // 3072   x buffer A: [e][h] 256x12 (transposed: X[d*12+h])
#define OFF_X1    3072     // 3072   x buffer B
#define OFF_RED   6144     // 12288  partials [16][12][64]
#define OFF_SCAL  18432    // 192    per-stage column scales [3][64]
#define OFF_COLC  18624    // 6144   correction values [3][64*CAP]
#define OFF_TBL   24768    // 16384  (u32) last-wins table [256][64]; reused as M-cache [256][64] f32
#define OFF_COLP7 41152    // 2048   (int) correction d-index [64*CAP]
#define OFF_CNT   43200    // 64     (int) per-column correction count
#define SMEM_FLOATS 43264
#define SMEM_BYTES (SMEM_FLOATS * 4)

extern __shared__ float smem[];

__global__ void __cluster_dims__(CLUSTER, 1, 1) __launch_bounds__(BLOCK, 1)
chain_kernel(const float* __restrict__ p1, const float* __restrict__ p2,
             const float* __restrict__ p3, const float* __restrict__ p4,
             const int* __restrict__ p5, const int* __restrict__ p6,
             const int* __restrict__ p7, const int* __restrict__ p8,
             const float* __restrict__ p9, const float* __restrict__ p10,
             const float* __restrict__ p11, const float* __restrict__ p12,
             const float* __restrict__ p13, const float* __restrict__ p14,
             const float* __restrict__ p15, const float* __restrict__ p16,
             float* __restrict__ out, int K)
{
    cg::cluster_group cluster = cg::this_cluster();
    const int tid  = (int)threadIdx.x;
    const int rank = (int)cluster.block_rank();      // 0..3
    const int b    = (int)blockIdx.x >> 2;           // batch 0..5
    const int e0   = rank * 64;                      // this CTA's column base

    float*    X0     = smem + OFF_X0;
    float*    X1     = smem + OFF_X1;
    float*    red    = smem + OFF_RED;
    float*    scal   = smem + OFF_SCAL;
    float*    colc   = smem + OFF_COLC;
    unsigned* tbl    = (unsigned*)(smem + OFF_TBL);
    float*    Mc     = smem + OFF_TBL;               // reuse after prep: M cache [d][el]
    int*      colp7  = (int*)(smem + OFF_COLP7);
    int*      colcnt = (int*)(smem + OFF_CNT);

    // ---------------- prep: clear table, load x0, compute mod scales ----------------
    {
        uint4* t4 = (uint4*)tbl;
        for (int i = tid; i < 4096; i += BLOCK) t4[i] = make_uint4(0u, 0u, 0u, 0u);
        if (tid < 64) colcnt[tid] = 0;

        // x0 = primals_2[h][b][:]  stored transposed: X0[d*12 + h]
        for (int i = tid; i < 3072; i += BLOCK) {
            int h = i >> 8, d = i & 255;
            X0[d * 12 + h] = p2[h * 1536 + b * 256 + d];
        }

        if (tid < 64) {
            float fr[3] = { p9[0],  p12[0], p15[0] };
            float ph[3] = { p10[0], p13[0], p16[0] };
            float t = (float)(e0 + tid);
            #pragma unroll
            for (int s = 0; s < 3; s++) {
                float a  = t * 6.2831853071795864f;  // rounds to f32 2*pi
                a = a * fr[s] + ph[s];
                float sv = sinf(a);
                float m  = sv * sv * 0.1f + 0.95f;
                scal[s * 64 + tid] = (s == 1) ? m : (1.0f / m);
            }
        }
    }
    __syncthreads();

    // ---------------- scatter dedup pass 1: last index wins ----------------
    for (int k = tid; k < K; k += BLOCK) {
        if (p5[k] == b) {
            int e8 = p8[k];
            if ((e8 >> 6) == rank)
                atomicMax(&tbl[p7[k] * 64 + (e8 & 63)], (unsigned)(k + 1));
        }
    }
    __syncthreads();

    // ---------------- scatter pass 2: build per-column correction lists ----------------
    for (int k = tid; k < K; k += BLOCK) {
        if (p5[k] == b) {
            int e8 = p8[k];
            if ((e8 >> 6) == rank) {
                int d7 = p7[k], el = e8 & 63;
                if (tbl[d7 * 64 + el] == (unsigned)(k + 1)) {     // winner
                    int   c6 = p6[k];
                    float pb = p1[b * 65536 + d7 * 256 + e8];
                    int j = atomicAdd(&colcnt[el], 1);
                    if (j < CAP) {
                        colp7[el * CAP + j] = d7;
                        colc[0 * 2048 + el * CAP + j] = p4 [b * 256 + c6] - pb;
                        colc[1 * 2048 + el * CAP + j] = p11[b * 256 + c6] - pb;
                        colc[2 * 2048 + el * CAP + j] = p14[b * 256 + c6] - pb;
                    }
                }
            }
        }
    }
    __syncthreads();   // tbl is dead past this point; region becomes Mc

    // ---------------- 3-stage chain ----------------
    const int dch = tid >> 5;      // 0..15 : d chunk (16 d each)
    const int ep  = tid & 31;      // 0..31 : column pair
    const int el2 = ep * 2;

    const float* P1 = p1 + b * 65536 + dch * 16 * 256 + e0 + el2;
    const float* P3 = p3 + b * 65536 + dch * 16 * 256 + e0 + el2;
    float* McBase = Mc + dch * 16 * 64 + el2;        // M[d][el] for this thread's lanes

    for (int s = 0; s < 3; s++) {
        const float* Xin  = (s & 1) ? X1 : X0;
        float*       Xout = (s & 1) ? X0 : X1;

        float acc[24];
        #pragma unroll
        for (int i = 0; i < 24; i++) acc[i] = 0.0f;

        const float4* X4 = (const float4*)(Xin + dch * 16 * 12);

        if (s == 0) {
            // stage 0: build M from global, cache in smem, consume
            #pragma unroll 4
            for (int i = 0; i < 16; i++) {
                float2 a = *(const float2*)(P1 + i * 256);
                float2 c = *(const float2*)(P3 + i * 256);
                float mx = fmaf(c.x, 0.975f, a.x);
                float my = fmaf(c.y, 0.975f, a.y);
                *(float2*)(McBase + i * 64) = make_float2(mx, my);
                float4 xa = X4[i * 3 + 0];
                float4 xb = X4[i * 3 + 1];
                float4 xc = X4[i * 3 + 2];
                acc[0]  += xa.x * mx;  acc[1]  += xa.x * my;
                acc[2]  += xa.y * mx;  acc[3]  += xa.y * my;
                acc[4]  += xa.z * mx;  acc[5]  += xa.z * my;
                acc[6]  += xa.w * mx;  acc[7]  += xa.w * my;
                acc[8]  += xb.x * mx;  acc[9]  += xb.x * my;
                acc[10] += xb.y * mx;  acc[11] += xb.y * my;
                acc[12] += xb.z * mx;  acc[13] += xb.z * my;
                acc[14] += xb.w * mx;  acc[15] += xb.w * my;
                acc[16] += xc.x * mx;  acc[17] += xc.x * my;
                acc[18] += xc.y * mx;  acc[19] += xc.y * my;
                acc[20] += xc.z * mx;  acc[21] += xc.z * my;
                acc[22] += xc.w * mx;  acc[23] += xc.w * my;
            }
        } else {
            // stages 1-2: M from smem cache
            #pragma unroll 4
            for (int i = 0; i < 16; i++) {
                float2 m2v = *(const float2*)(McBase + i * 64);
                float mx = m2v.x, my = m2v.y;
                float4 xa = X4[i * 3 + 0];
                float4 xb = X4[i * 3 + 1];
                float4 xc = X4[i * 3 + 2];
                acc[0]  += xa.x * mx;  acc[1]  += xa.x * my;
                acc[2]  += xa.y * mx;  acc[3]  += xa.y * my;
                acc[4]  += xa.z * mx;  acc[5]  += xa.z * my;
                acc[6]  += xa.w * mx;  acc[7]  += xa.w * my;
                acc[8]  += xb.x * mx;  acc[9]  += xb.x * my;
                acc[10] += xb.y * mx;  acc[11] += xb.y * my;
                acc[12] += xb.z * mx;  acc[13] += xb.z * my;
                acc[14] += xb.w * mx;  acc[15] += xb.w * my;
                acc[16] += xc.x * mx;  acc[17] += xc.x * my;
                acc[18] += xc.y * mx;  acc[19] += xc.y * my;
                acc[20] += xc.z * mx;  acc[21] += xc.z * my;
                acc[22] += xc.w * mx;  acc[23] += xc.w * my;
            }
        }

        // sparse scatter corrections (warp 0 only; ~1.3 entries/column avg)
        if (dch == 0) {
            #pragma unroll
            for (int cc = 0; cc < 2; cc++) {
                int elc = el2 + cc;
                int n = colcnt[elc]; if (n > CAP) n = CAP;
                for (int j = 0; j < n; j++) {
                    int   d7 = colp7[elc * CAP + j];
                    float cv = colc[s * 2048 + elc * CAP + j];
                    const float4* xr = (const float4*)(Xin + d7 * 12);
                    float4 xa = xr[0], xb = xr[1], xc = xr[2];
                    acc[0  + cc] += xa.x * cv;  acc[2  + cc] += xa.y * cv;
                    acc[4  + cc] += xa.z * cv;  acc[6  + cc] += xa.w * cv;
                    acc[8  + cc] += xb.x * cv;  acc[10 + cc] += xb.y * cv;
                    acc[12 + cc] += xb.z * cv;  acc[14 + cc] += xb.w * cv;
                    acc[16 + cc] += xc.x * cv;  acc[18 + cc] += xc.y * cv;
                    acc[20 + cc] += xc.z * cv;  acc[22 + cc] += xc.w * cv;
                }
            }
        }

        // write partials
        #pragma unroll
        for (int h = 0; h < 12; h++)
            *(float2*)&red[(dch * 12 + h) * 64 + el2] =
                make_float2(acc[2 * h], acc[2 * h + 1]);
        __syncthreads();

        // reduce 16 partials, apply mod scale, emit
        for (int o = tid; o < 768; o += BLOCK) {
            int h = o >> 6, elc = o & 63;
            float sum = 0.0f;
            #pragma unroll
            for (int dc = 0; dc < 16; dc++) sum += red[(dc * 12 + h) * 64 + elc];
            sum *= scal[s * 64 + elc];
            if (s < 2) Xout[(e0 + elc) * 12 + h] = sum;
            else       out[h * 1536 + b * 256 + e0 + elc] = sum;
        }

        if (s < 2) {
            cluster.sync();   // own segment of Xout visible cluster-wide
            // pull 3 peer segments (192 float4 each) into local Xout
            for (int i = tid; i < 576; i += BLOCK) {
                int pidx = i / 192;          // 0..2
                int off  = i % 192;
                unsigned sr = (unsigned)((rank + 1 + pidx) & 3);
                float* dst = Xout + sr * 768 + off * 4;
                const float* peer = cluster.map_shared_rank(dst, sr);
                *(float4*)dst = *(const float4*)peer;
            }
            __syncthreads();
        }
    }

    cluster.sync();   // no CTA exits while peers may still read its SMEM
}

extern "C" void kernel_launch(void* const* d_in, const int* in_sizes, int n_in,
                              void* d_out, int out_size)
{
    (void)n_in; (void)out_size;
    cudaFuncSetAttribute(chain_kernel,
                         cudaFuncAttributeMaxDynamicSharedMemorySize, SMEM_BYTES);
    chain_kernel<<<6 * CLUSTER, BLOCK, SMEM_BYTES>>>(
        (const float*)d_in[0],  (const float*)d_in[1],
        (const float*)d_in[2],  (const float*)d_in[3],
        (const int*)  d_in[4],  (const int*)  d_in[5],
        (const int*)  d_in[6],  (const int*)  d_in[7],
        (const float*)d_in[8],  (const float*)d_in[9],
        (const float*)d_in[10], (const float*)d_in[11],
        (const float*)d_in[12], (const float*)d_in[13],
        (const float*)d_in[14], (const float*)d_in[15],
        (float*)d_out, in_sizes[4]);
}